// round 1
// baseline (speedup 1.0000x reference)
#include <cuda_runtime.h>
#include <cuda_bf16.h>
#include <cstdint>

#define NREG   10000
#define NBINS  32
#define NPTS_PER_THREAD 4

// Scratch (device globals are the sanctioned scratch mechanism).
// Per (region, bin): 2 x float4 = 32 bytes, 32B-aligned -> one L2 sector.
//   p0 = {bl_l, bl_r, inv_w, cdf_l}
//   p1 = {h_l, dh(=h_r-h_l), 0, 0}
__device__ __align__(32) float4 g_params[NREG * NBINS * 2];   // 10.24 MB
__device__ unsigned char g_lut[NREG * 256];                    // 2.56 MB

// ---------------------------------------------------------------------------
// Kernel 1: one warp per region. Computes softmax widths, normalized heights,
// cumsums, packs the per-bin structs, and builds the 256-entry bucket LUT.
// ---------------------------------------------------------------------------
__global__ void __launch_bounds__(256)
spline_prep_kernel(const float* __restrict__ uw, const float* __restrict__ uh)
{
    __shared__ float s_bl[8][33];

    const int warp = threadIdx.x >> 5;
    const int lane = threadIdx.x & 31;
    const int r    = blockIdx.x * 8 + warp;
    if (r >= NREG) return;

    const float w_logit = uw[r * NBINS + lane];
    const float h_logit = uh[r * (NBINS + 1) + lane];
    const float h_last  = uh[r * (NBINS + 1) + NBINS];   // broadcast load

    // --- softmax over widths ---
    float m = w_logit;
    #pragma unroll
    for (int o = 16; o; o >>= 1) m = fmaxf(m, __shfl_xor_sync(0xffffffffu, m, o));
    float e = __expf(w_logit - m);
    float s = e;
    #pragma unroll
    for (int o = 16; o; o >>= 1) s += __shfl_xor_sync(0xffffffffu, s, o);
    const float w = e / s;

    // --- heights: exp, normalize by trapezoid area ---
    float hexp   = __expf(h_logit);
    float hexp_n = __shfl_down_sync(0xffffffffu, hexp, 1);
    if (lane == 31) hexp_n = __expf(h_last);

    float area = 0.5f * (hexp + hexp_n) * w;
    #pragma unroll
    for (int o = 16; o; o >>= 1) area += __shfl_xor_sync(0xffffffffu, area, o);
    const float inv_area = 1.0f / area;
    const float hl = hexp * inv_area;
    const float hr = hexp_n * inv_area;

    // --- inclusive scans: cdf over trapezoids, locs over widths ---
    float cdf = 0.5f * (hl + hr) * w;
    float loc = w;
    #pragma unroll
    for (int o = 1; o < 32; o <<= 1) {
        const float c = __shfl_up_sync(0xffffffffu, cdf, o);
        const float l = __shfl_up_sync(0xffffffffu, loc, o);
        if (lane >= o) { cdf += c; loc += l; }
    }
    float cdf_l = __shfl_up_sync(0xffffffffu, cdf, 1); if (lane == 0) cdf_l = 0.0f;
    float bl_l  = __shfl_up_sync(0xffffffffu, loc, 1); if (lane == 0) bl_l  = 0.0f;
    const float bl_r = (lane == 31) ? 1.0f : loc;      // reference sets last loc = 1.0

    // --- pack per-bin struct ---
    float4* p = g_params + (size_t)(r * NBINS + lane) * 2;
    p[0] = make_float4(bl_l, bl_r, 1.0f / w, cdf_l);
    p[1] = make_float4(hl, hr - hl, 0.0f, 0.0f);

    // --- LUT: lut[b] = max k such that bl[k] <= b/256 (a lower bound on the bin) ---
    s_bl[warp][lane] = bl_l;
    if (lane == 31) s_bl[warp][32] = 1.0f;
    __syncwarp();

    unsigned char* lut = g_lut + (size_t)r * 256;
    #pragma unroll
    for (int j = 0; j < 8; j++) {
        const int b   = lane + j * 32;
        const float v = (float)b * (1.0f / 256.0f);   // exact (power of 2)
        int k = 0;
        #pragma unroll
        for (int st = 16; st >= 1; st >>= 1) {
            const int t = k + st;
            if (t <= 32 && s_bl[warp][t] <= v) k = t;
        }
        // bl[32] = 1.0 > v guarantees k <= 31
        lut[b] = (unsigned char)k;
    }
}

// ---------------------------------------------------------------------------
// Kernel 2: 4 points per thread, staged loads for MLP. LUT gives a lower-bound
// bin; forward-refine on bl_r (expected ~0.125 extra iterations).
// ---------------------------------------------------------------------------
__global__ void __launch_bounds__(256)
spline_eval_kernel(const float* __restrict__ x, const int* __restrict__ ix,
                   float* __restrict__ out, float* __restrict__ lad, int n)
{
    const int i0 = (blockIdx.x * blockDim.x + threadIdx.x) * NPTS_PER_THREAD;
    if (i0 >= n) return;   // n % 4 == 0, so full vectors when active

    const float4 xv4 = *reinterpret_cast<const float4*>(x + i0);
    const int4   r4  = *reinterpret_cast<const int4*>(ix + i0);

    float xs[4] = { xv4.x, xv4.y, xv4.z, xv4.w };
    int   rs[4] = { r4.x, r4.y, r4.z, r4.w };

    // Stage 1: 4 independent LUT byte loads
    int k[4];
    #pragma unroll
    for (int j = 0; j < 4; j++) {
        const int b = min((int)(xs[j] * 256.0f), 255);
        k[j] = g_lut[(size_t)rs[j] * 256 + b];
    }

    // Stage 2: 4 independent struct loads + rare refinement
    float4 p0[4];
    const float4* base[4];
    #pragma unroll
    for (int j = 0; j < 4; j++) {
        base[j] = g_params + (size_t)rs[j] * (NBINS * 2);
        p0[j] = __ldg(base[j] + k[j] * 2);
    }
    #pragma unroll
    for (int j = 0; j < 4; j++) {
        while (xs[j] >= p0[j].y && k[j] < NBINS - 1) {   // x >= bl_r -> next bin
            k[j]++;
            p0[j] = __ldg(base[j] + k[j] * 2);
        }
    }

    // Stage 3: second half of each struct (same 32B sector as p0)
    float4 p1[4];
    #pragma unroll
    for (int j = 0; j < 4; j++) p1[j] = __ldg(base[j] + k[j] * 2 + 1);

    // Compute: out = cdf_l + (x-bl_l)*(h_l + 0.5*dh*alpha); lad = log(alpha*dh + h_l)
    float o[4], l[4];
    #pragma unroll
    for (int j = 0; j < 4; j++) {
        const float t     = xs[j] - p0[j].x;
        const float alpha = t * p0[j].z;
        o[j] = fmaf(t, fmaf(0.5f * p1[j].y, alpha, p1[j].x), p0[j].w);
        l[j] = __logf(fmaf(alpha, p1[j].y, p1[j].x));
    }

    *reinterpret_cast<float4*>(out + i0) = make_float4(o[0], o[1], o[2], o[3]);
    *reinterpret_cast<float4*>(lad + i0) = make_float4(l[0], l[1], l[2], l[3]);
}

// ---------------------------------------------------------------------------
extern "C" void kernel_launch(void* const* d_in, const int* in_sizes, int n_in,
                              void* d_out, int out_size)
{
    const float* x  = (const float*)d_in[0];
    const int*   ix = (const int*)d_in[1];
    const float* uw = (const float*)d_in[2];
    const float* uh = (const float*)d_in[3];

    const int n = in_sizes[0];                   // 2,000,000 points
    float* out = (float*)d_out;                  // outputs[0:n]
    float* lad = (float*)d_out + n;              // logabsdet[n:2n]

    // Kernel 1: 8 warps/block, one warp per region
    const int prep_blocks = (NREG + 7) / 8;
    spline_prep_kernel<<<prep_blocks, 256>>>(uw, uh);

    // Kernel 2: 4 points/thread
    const int threads = 256;
    const int per_block = threads * NPTS_PER_THREAD;
    const int eval_blocks = (n + per_block - 1) / per_block;
    spline_eval_kernel<<<eval_blocks, threads>>>(x, ix, out, lad, n);
}

// round 2
// speedup vs baseline: 1.5562x; 1.5562x over previous
#include <cuda_runtime.h>
#include <cuda_bf16.h>
#include <cstdint>

#define NREG     10000
#define NBINS    32
#define NBUCKETS 128
#define NPTS_PER_THREAD 4

// Scratch (device globals are the sanctioned scratch mechanism).
// Bin struct (16 B): {bl_l, cdf_l, h_l, A = (h_r - h_l)/w}
__device__ __align__(16) float4 g_bins16[NREG * NBINS];        // 5.12 MB
// Bucket-direct table: bucket b holds the struct of the UPPER-BOUND bin for
// x in [b/128, (b+1)/128), with the bin index k packed into the low 5
// mantissa bits of A (for the rare backward-refinement fallback).
__device__ __align__(16) float4 g_buckets[NREG * NBUCKETS];    // 20.48 MB

// ---------------------------------------------------------------------------
// Kernel 1: one warp per region. Softmax widths, normalized heights, scans,
// then writes the 32-entry bin table and the 128-entry bucket-direct table.
// ---------------------------------------------------------------------------
__global__ void __launch_bounds__(256)
spline_prep_kernel(const float* __restrict__ uw, const float* __restrict__ uh)
{
    __shared__ float  s_bl[8][33];
    __shared__ float4 s_e[8][32];

    const int warp = threadIdx.x >> 5;
    const int lane = threadIdx.x & 31;
    const int r    = blockIdx.x * 8 + warp;
    if (r >= NREG) return;

    const float w_logit = uw[r * NBINS + lane];
    const float h_logit = uh[r * (NBINS + 1) + lane];
    const float h_last  = uh[r * (NBINS + 1) + NBINS];

    // --- softmax over widths ---
    float m = w_logit;
    #pragma unroll
    for (int o = 16; o; o >>= 1) m = fmaxf(m, __shfl_xor_sync(0xffffffffu, m, o));
    float e = __expf(w_logit - m);
    float s = e;
    #pragma unroll
    for (int o = 16; o; o >>= 1) s += __shfl_xor_sync(0xffffffffu, s, o);
    const float w = e / s;

    // --- heights: exp, normalize by trapezoid area ---
    float hexp   = __expf(h_logit);
    float hexp_n = __shfl_down_sync(0xffffffffu, hexp, 1);
    if (lane == 31) hexp_n = __expf(h_last);

    float area = 0.5f * (hexp + hexp_n) * w;
    #pragma unroll
    for (int o = 16; o; o >>= 1) area += __shfl_xor_sync(0xffffffffu, area, o);
    const float inv_area = 1.0f / area;
    const float hl = hexp * inv_area;
    const float hr = hexp_n * inv_area;

    // --- inclusive scans: cdf over trapezoids, locs over widths ---
    float cdf = 0.5f * (hl + hr) * w;
    float loc = w;
    #pragma unroll
    for (int o = 1; o < 32; o <<= 1) {
        const float c = __shfl_up_sync(0xffffffffu, cdf, o);
        const float l = __shfl_up_sync(0xffffffffu, loc, o);
        if (lane >= o) { cdf += c; loc += l; }
    }
    float cdf_l = __shfl_up_sync(0xffffffffu, cdf, 1); if (lane == 0) cdf_l = 0.0f;
    float bl_l  = __shfl_up_sync(0xffffffffu, loc, 1); if (lane == 0) bl_l  = 0.0f;

    // --- 16B bin struct ---
    const float A = (hr - hl) / w;
    const float4 ebin = make_float4(bl_l, cdf_l, hl, A);
    g_bins16[r * NBINS + lane] = ebin;
    s_e[warp][lane]  = ebin;
    s_bl[warp][lane] = bl_l;
    if (lane == 31) s_bl[warp][32] = 1.0f;
    __syncwarp();

    // --- bucket-direct table: k_ub = max k<=31 with bl[k] <= (b+1)/128 ---
    float4* buckets = g_buckets + (size_t)r * NBUCKETS;
    #pragma unroll
    for (int j = 0; j < NBUCKETS / 32; j++) {
        const int b   = lane + j * 32;
        const float v = (float)(b + 1) * (1.0f / (float)NBUCKETS);  // exact
        int k = 0;
        #pragma unroll
        for (int st = 16; st >= 1; st >>= 1) {
            const int t = k + st;
            if (t <= 31 && s_bl[warp][t] <= v) k = t;
        }
        float4 ek = s_e[warp][k];
        // steal low 5 mantissa bits of A for the bin index
        ek.w = __uint_as_float((__float_as_uint(ek.w) & ~31u) | (unsigned)k);
        buckets[b] = ek;
    }
}

// ---------------------------------------------------------------------------
// Kernel 2: 4 points/thread. ONE divergent 16B load per point (bucket-direct);
// ~12.5% of points take a backward-refinement load from the bin table.
// ---------------------------------------------------------------------------
__global__ void __launch_bounds__(256)
spline_eval_kernel(const float* __restrict__ x, const int* __restrict__ ix,
                   float* __restrict__ out, float* __restrict__ lad, int n)
{
    const int i0 = (blockIdx.x * blockDim.x + threadIdx.x) * NPTS_PER_THREAD;
    if (i0 >= n) return;   // n % 4 == 0

    const float4 xv4 = *reinterpret_cast<const float4*>(x + i0);
    const int4   r4  = *reinterpret_cast<const int4*>(ix + i0);

    float xs[4] = { xv4.x, xv4.y, xv4.z, xv4.w };
    int   rs[4] = { r4.x, r4.y, r4.z, r4.w };

    // Stage 1: 4 independent bucket loads (the only divergent fast-path loads)
    float4 e[4];
    #pragma unroll
    for (int j = 0; j < 4; j++) {
        const int b = min((int)(xs[j] * (float)NBUCKETS), NBUCKETS - 1);
        e[j] = __ldg(g_buckets + (size_t)rs[j] * NBUCKETS + b);
    }

    // Stage 2: rare backward refinement (x left of the upper-bound bin)
    #pragma unroll
    for (int j = 0; j < 4; j++) {
        if (xs[j] < e[j].x) {
            int k = (int)(__float_as_uint(e[j].w) & 31u);
            do {
                k--;
                e[j] = __ldg(g_bins16 + (size_t)rs[j] * NBINS + k);
            } while (k > 0 && xs[j] < e[j].x);
        }
    }

    // Compute: out = cdf_l + t*(h_l + 0.5*A*t);  lad = log(h_l + A*t)
    float o[4], l[4];
    #pragma unroll
    for (int j = 0; j < 4; j++) {
        const float t = xs[j] - e[j].x;
        o[j] = fmaf(t, fmaf(0.5f * e[j].w, t, e[j].z), e[j].y);
        l[j] = __logf(fmaf(e[j].w, t, e[j].z));
    }

    *reinterpret_cast<float4*>(out + i0) = make_float4(o[0], o[1], o[2], o[3]);
    *reinterpret_cast<float4*>(lad + i0) = make_float4(l[0], l[1], l[2], l[3]);
}

// ---------------------------------------------------------------------------
extern "C" void kernel_launch(void* const* d_in, const int* in_sizes, int n_in,
                              void* d_out, int out_size)
{
    const float* x  = (const float*)d_in[0];
    const int*   ix = (const int*)d_in[1];
    const float* uw = (const float*)d_in[2];
    const float* uh = (const float*)d_in[3];

    const int n = in_sizes[0];                   // 2,000,000 points
    float* out = (float*)d_out;                  // outputs[0:n]
    float* lad = (float*)d_out + n;              // logabsdet[n:2n]

    const int prep_blocks = (NREG + 7) / 8;
    spline_prep_kernel<<<prep_blocks, 256>>>(uw, uh);

    const int threads = 256;
    const int per_block = threads * NPTS_PER_THREAD;
    const int eval_blocks = (n + per_block - 1) / per_block;
    spline_eval_kernel<<<eval_blocks, threads>>>(x, ix, out, lad, n);
}